// round 4
// baseline (speedup 1.0000x reference)
#include <cuda_runtime.h>
#include <cstdint>
#include <math.h>

#define N_NODES 50000
#define N_EDGES 800000
#define IN_FEAT 512
#define OUT_FEAT 128

// Scratch: intermediate x = feat @ W, CSR row pointers, fragment-ordered W.
__device__ float  g_x[(size_t)N_NODES * OUT_FEAT];
__device__ int    g_row_ptr[N_NODES + 1];
// B fragments: idx = (kk*16 + nbg)*32 + lane, value {B[kk*8+t4][n], B[kk*8+t4+4][n]}
// with t4 = lane&3, g = lane>>2, n = nbg*8 + g;  kk = 0..63, nbg = 0..15.
__device__ float2 g_Bfrag[64 * 16 * 32];

// ---------------------------------------------------------------------------
// Kernel 1: CSR row pointers via vectorized edge-boundary scatter.
// rows sorted ascending; row_ptr[i] = first e with rows[e] >= i.
// ---------------------------------------------------------------------------
__global__ void row_ptr_kernel(const int* __restrict__ rows) {
    const int t = blockIdx.x * blockDim.x + threadIdx.x;
    const int e0 = t * 4;
    if (e0 >= N_EDGES) return;
    const int4 r4 = *(const int4*)&rows[e0];
    int prev = (t == 0) ? -1 : __ldg(&rows[e0 - 1]);
    int rv[4] = {r4.x, r4.y, r4.z, r4.w};
    #pragma unroll
    for (int j = 0; j < 4; ++j) {
        for (int r = prev + 1; r <= rv[j]; ++r) g_row_ptr[r] = e0 + j;
        prev = rv[j];
    }
    if (e0 + 4 == N_EDGES) {
        for (int r = prev + 1; r <= N_NODES; ++r) g_row_ptr[r] = N_EDGES;
    }
}

// ---------------------------------------------------------------------------
// Kernel 1b: permute weight into MMA fragment order (raw fp32, split later).
// ---------------------------------------------------------------------------
__global__ void bfrag_kernel(const float* __restrict__ B) {
    const int idx = blockIdx.x * blockDim.x + threadIdx.x;   // 0..32767
    if (idx >= 64 * 16 * 32) return;
    const int lane = idx & 31;
    const int nbg  = (idx >> 5) & 15;
    const int kk   = idx >> 9;
    const int t4   = lane & 3;
    const int g    = lane >> 2;
    const int n    = nbg * 8 + g;
    const int k    = kk * 8 + t4;
    g_Bfrag[idx] = make_float2(__ldg(&B[(size_t)k * OUT_FEAT + n]),
                               __ldg(&B[(size_t)(k + 4) * OUT_FEAT + n]));
}

// ---------------------------------------------------------------------------
// Kernel 2: 3xTF32 GEMM via mma.sync, software-pipelined.
//   g_x[M,128] = feat[M,512] @ W[512,128]
// CTA 128x128, 8 warps (4m x 2n), warp tile 32x64, K chunks of 32.
// A: raw fp32 in double-buffered SMEM (stride 36, conflict-free), hi/lo split
//    in registers. B: raw fragments straight from L1-resident g_Bfrag (LDG.64),
//    split in registers. hh + hl + lh accumulated in fp32 (~2^-21 rel error).
// ---------------------------------------------------------------------------
#define BM 128
#define KC 32
#define NCHUNK (IN_FEAT / KC)     // 16
#define A_STRIDE 36               // floats per A smem row (32 + 4 pad)

__device__ __forceinline__ float tf32_hi(float x) {
    return __uint_as_float(__float_as_uint(x) & 0xFFFFE000u);
}

#define MMA_TF32(cc, aa, b0, b1)                                               \
    asm volatile(                                                              \
        "mma.sync.aligned.m16n8k8.row.col.f32.tf32.tf32.f32 "                  \
        "{%0,%1,%2,%3}, {%4,%5,%6,%7}, {%8,%9}, {%0,%1,%2,%3};"                \
        : "+f"((cc)[0]), "+f"((cc)[1]), "+f"((cc)[2]), "+f"((cc)[3])           \
        : "r"((aa)[0]), "r"((aa)[1]), "r"((aa)[2]), "r"((aa)[3]),              \
          "r"(b0), "r"(b1))

__global__ __launch_bounds__(256, 2) void gemm_mma_kernel(
    const float* __restrict__ A)   // feat [N_NODES, 512]
{
    __shared__ float sA[2][BM * A_STRIDE];   // 2 x 18 KB

    const int tid  = threadIdx.x;
    const int wid  = tid >> 5;
    const int lane = tid & 31;
    const int g    = lane >> 2;    // 0..7
    const int t4   = lane & 3;     // 0..3
    const int wm   = wid & 3;      // warp m index
    const int wn   = wid >> 2;     // warp n index
    const int m0   = blockIdx.x * BM;

    // fill mapping: thread owns 4 (m, k4) slots per chunk
    const int fm[4] = { (0 * 256 + tid) >> 3, (1 * 256 + tid) >> 3,
                        (2 * 256 + tid) >> 3, (3 * 256 + tid) >> 3 };
    const int fk4   = tid & 7;

    float c[2][8][4];
    #pragma unroll
    for (int i = 0; i < 2; i++)
        #pragma unroll
        for (int j = 0; j < 8; j++)
            #pragma unroll
            for (int q = 0; q < 4; q++) c[i][j][q] = 0.0f;

    // ---- prologue: load + store chunk 0 ----
    float4 pf[4];
    #pragma unroll
    for (int it = 0; it < 4; ++it) {
        const int gm = m0 + fm[it];
        pf[it] = make_float4(0.f, 0.f, 0.f, 0.f);
        if (gm < N_NODES)
            pf[it] = *(const float4*)&A[(size_t)gm * IN_FEAT + fk4 * 4];
    }
    #pragma unroll
    for (int it = 0; it < 4; ++it)
        *(float4*)&sA[0][fm[it] * A_STRIDE + fk4 * 4] = pf[it];
    __syncthreads();

    for (int ch = 0; ch < NCHUNK; ++ch) {
        const int buf = ch & 1;

        // prefetch next chunk's A (latency hidden under compute)
        if (ch + 1 < NCHUNK) {
            const int k0n = (ch + 1) * KC;
            #pragma unroll
            for (int it = 0; it < 4; ++it) {
                const int gm = m0 + fm[it];
                pf[it] = make_float4(0.f, 0.f, 0.f, 0.f);
                if (gm < N_NODES)
                    pf[it] = *(const float4*)&A[(size_t)gm * IN_FEAT + k0n + fk4 * 4];
            }
        }

        // ---- compute chunk ch ----
        const float* sa = sA[buf];
        #pragma unroll
        for (int ks = 0; ks < 4; ++ks) {
            const int kb = ks * 8;
            const int kk = ch * 4 + ks;

            // B raw fragments for this k8-step (8 n-blocks)
            float2 braw[8];
            #pragma unroll
            for (int nb = 0; nb < 8; ++nb)
                braw[nb] = __ldg(&g_Bfrag[(size_t)(kk * 16 + wn * 8 + nb) * 32 + lane]);

            // A fragments: raw LDS then register split
            uint32_t ah[2][4], al[2][4];
            #pragma unroll
            for (int mb = 0; mb < 2; ++mb) {
                const int r0 = wm * 32 + mb * 16 + g;
                const float a0 = sa[r0 * A_STRIDE + kb + t4];
                const float a1 = sa[(r0 + 8) * A_STRIDE + kb + t4];
                const float a2 = sa[r0 * A_STRIDE + kb + t4 + 4];
                const float a3 = sa[(r0 + 8) * A_STRIDE + kb + t4 + 4];
                const float h0 = tf32_hi(a0), h1 = tf32_hi(a1);
                const float h2 = tf32_hi(a2), h3 = tf32_hi(a3);
                ah[mb][0] = __float_as_uint(h0); al[mb][0] = __float_as_uint(a0 - h0);
                ah[mb][1] = __float_as_uint(h1); al[mb][1] = __float_as_uint(a1 - h1);
                ah[mb][2] = __float_as_uint(h2); al[mb][2] = __float_as_uint(a2 - h2);
                ah[mb][3] = __float_as_uint(h3); al[mb][3] = __float_as_uint(a3 - h3);
            }

            #pragma unroll
            for (int nb = 0; nb < 8; ++nb) {
                const float bh0f = tf32_hi(braw[nb].x);
                const float bh1f = tf32_hi(braw[nb].y);
                const uint32_t bh0 = __float_as_uint(bh0f);
                const uint32_t bh1 = __float_as_uint(bh1f);
                const uint32_t bl0 = __float_as_uint(braw[nb].x - bh0f);
                const uint32_t bl1 = __float_as_uint(braw[nb].y - bh1f);
                #pragma unroll
                for (int mb = 0; mb < 2; ++mb) {
                    MMA_TF32(c[mb][nb], ah[mb], bh0, bh1);   // hi*hi
                    MMA_TF32(c[mb][nb], ah[mb], bl0, bl1);   // hi*lo
                    MMA_TF32(c[mb][nb], al[mb], bh0, bh1);   // lo*hi
                }
            }
        }

        // store prefetched chunk into the other buffer
        // (safe: its readers finished before the sync that ended chunk ch-1)
        if (ch + 1 < NCHUNK) {
            #pragma unroll
            for (int it = 0; it < 4; ++it)
                *(float4*)&sA[buf ^ 1][fm[it] * A_STRIDE + fk4 * 4] = pf[it];
        }
        __syncthreads();
    }

    // ---- epilogue ----
    #pragma unroll
    for (int mb = 0; mb < 2; ++mb) {
        #pragma unroll
        for (int half = 0; half < 2; ++half) {
            const int row = m0 + wm * 32 + mb * 16 + g + half * 8;
            if (row < N_NODES) {
                #pragma unroll
                for (int nb = 0; nb < 8; ++nb) {
                    const int col = wn * 64 + nb * 8 + 2 * t4;
                    float2 v = make_float2(c[mb][nb][2 * half],
                                           c[mb][nb][2 * half + 1]);
                    *(float2*)&g_x[(size_t)row * OUT_FEAT + col] = v;
                }
            }
        }
    }
}

// ---------------------------------------------------------------------------
// Kernel 3: SpMM (warp per row, no atomics) + multispike epilogue.
// ---------------------------------------------------------------------------
__device__ __forceinline__ float multispike(float x) {
    return floorf(fminf(fmaxf(4.0f * x, 0.0f), 4.0f) + 0.5f) * 0.25f;
}

__global__ __launch_bounds__(256) void spmm_kernel(
    const int*   __restrict__ cols,
    const float* __restrict__ ew,
    float*       __restrict__ out)
{
    const int warp = (blockIdx.x * blockDim.x + threadIdx.x) >> 5;
    const int lane = threadIdx.x & 31;
    if (warp >= N_NODES) return;

    const int e0 = g_row_ptr[warp];
    const int e1 = g_row_ptr[warp + 1];

    float4 acc = make_float4(0.f, 0.f, 0.f, 0.f);
    const int fo = lane * 4;

    int e = e0;
    for (; e + 3 < e1; e += 4) {
        int   cc[4];
        float ww[4];
        #pragma unroll
        for (int j = 0; j < 4; ++j) { cc[j] = __ldg(&cols[e + j]); ww[j] = __ldg(&ew[e + j]); }
        #pragma unroll
        for (int j = 0; j < 4; ++j) {
            const float4 v = *(const float4*)&g_x[(size_t)cc[j] * OUT_FEAT + fo];
            acc.x = fmaf(ww[j], v.x, acc.x); acc.y = fmaf(ww[j], v.y, acc.y);
            acc.z = fmaf(ww[j], v.z, acc.z); acc.w = fmaf(ww[j], v.w, acc.w);
        }
    }
    for (; e < e1; ++e) {
        const int   c0 = __ldg(&cols[e]);
        const float w0 = __ldg(&ew[e]);
        const float4 v0 = *(const float4*)&g_x[(size_t)c0 * OUT_FEAT + fo];
        acc.x = fmaf(w0, v0.x, acc.x); acc.y = fmaf(w0, v0.y, acc.y);
        acc.z = fmaf(w0, v0.z, acc.z); acc.w = fmaf(w0, v0.w, acc.w);
    }

    acc.x = multispike(acc.x);
    acc.y = multispike(acc.y);
    acc.z = multispike(acc.z);
    acc.w = multispike(acc.w);
    *(float4*)&out[(size_t)warp * OUT_FEAT + fo] = acc;
}

// ---------------------------------------------------------------------------
extern "C" void kernel_launch(void* const* d_in, const int* in_sizes, int n_in,
                              void* d_out, int out_size) {
    const float* feat   = (const float*)d_in[0];
    const float* weight = (const float*)d_in[1];
    const int*   rows   = (const int*)d_in[2];
    const int*   cols   = (const int*)d_in[3];
    const float* ew     = (const float*)d_in[4];
    float* out = (float*)d_out;

    row_ptr_kernel<<<(N_EDGES / 4 + 255) / 256, 256>>>(rows);
    bfrag_kernel<<<(64 * 16 * 32 + 255) / 256, 256>>>(weight);
    gemm_mma_kernel<<<(N_NODES + BM - 1) / BM, 256>>>(feat);
    spmm_kernel<<<(N_NODES * 32 + 255) / 256, 256>>>(cols, ew, out);
}

// round 5
// speedup vs baseline: 1.2595x; 1.2595x over previous
#include <cuda_runtime.h>
#include <cstdint>
#include <math.h>

#define N_NODES 50000
#define N_EDGES 800000
#define IN_FEAT 512
#define OUT_FEAT 128

// Scratch: intermediate x = feat @ W, CSR row pointers, fragment-ordered W.
__device__ float  g_x[(size_t)N_NODES * OUT_FEAT];
__device__ int    g_row_ptr[N_NODES + 1];
// B fragments: idx = (kk*16 + nbg)*32 + lane, value {B[kk*8+t4][n], B[kk*8+t4+4][n]}
// with t4 = lane&3, g = lane>>2, n = nbg*8 + g;  kk = 0..63, nbg = 0..15.
__device__ float2 g_Bfrag[64 * 16 * 32];

// ---------------------------------------------------------------------------
// cp.async helpers (Ampere+ PTX, arch-portable — no 'a'-feature needed)
// ---------------------------------------------------------------------------
__device__ __forceinline__ uint32_t smem_u32(const void* p) {
    uint32_t a;
    asm("{ .reg .u64 t; cvta.to.shared.u64 t, %1; cvt.u32.u64 %0, t; }"
        : "=r"(a) : "l"(p));
    return a;
}
__device__ __forceinline__ void cp16(uint32_t dst, const void* src, int src_bytes) {
    asm volatile("cp.async.cg.shared.global [%0], [%1], 16, %2;"
                 :: "r"(dst), "l"(src), "r"(src_bytes));
}
__device__ __forceinline__ void cp_commit() {
    asm volatile("cp.async.commit_group;" ::: "memory");
}
template <int N>
__device__ __forceinline__ void cp_wait() {
    asm volatile("cp.async.wait_group %0;" :: "n"(N) : "memory");
}

// ---------------------------------------------------------------------------
// Kernel 1: CSR row pointers via vectorized edge-boundary scatter.
// ---------------------------------------------------------------------------
__global__ void row_ptr_kernel(const int* __restrict__ rows) {
    const int t = blockIdx.x * blockDim.x + threadIdx.x;
    const int e0 = t * 4;
    if (e0 >= N_EDGES) return;
    const int4 r4 = *(const int4*)&rows[e0];
    int prev = (t == 0) ? -1 : __ldg(&rows[e0 - 1]);
    int rv[4] = {r4.x, r4.y, r4.z, r4.w};
    #pragma unroll
    for (int j = 0; j < 4; ++j) {
        for (int r = prev + 1; r <= rv[j]; ++r) g_row_ptr[r] = e0 + j;
        prev = rv[j];
    }
    if (e0 + 4 == N_EDGES) {
        for (int r = prev + 1; r <= N_NODES; ++r) g_row_ptr[r] = N_EDGES;
    }
}

// ---------------------------------------------------------------------------
// Kernel 1b: permute weight into MMA fragment order (raw fp32, split later).
// ---------------------------------------------------------------------------
__global__ void bfrag_kernel(const float* __restrict__ B) {
    const int idx = blockIdx.x * blockDim.x + threadIdx.x;   // 0..32767
    if (idx >= 64 * 16 * 32) return;
    const int lane = idx & 31;
    const int nbg  = (idx >> 5) & 15;
    const int kk   = idx >> 9;
    const int t4   = lane & 3;
    const int g    = lane >> 2;
    const int n    = nbg * 8 + g;
    const int k    = kk * 8 + t4;
    g_Bfrag[idx] = make_float2(__ldg(&B[(size_t)k * OUT_FEAT + n]),
                               __ldg(&B[(size_t)(k + 4) * OUT_FEAT + n]));
}

// ---------------------------------------------------------------------------
// Kernel 2: 3xTF32 GEMM via mma.sync, cp.async double-buffered pipeline.
//   g_x[M,128] = feat[M,512] @ W[512,128]
// CTA 128x128, 8 warps (4m x 2n), warp tile 32x64, K chunks of 32.
// A raw fp32 in SMEM (stride 36, conflict-free); B fragment-ordered raw float2
// in SMEM (copied from g_Bfrag). hi/lo tf32 split in registers; accumulate
// hh + hl + lh in fp32 (~2^-21 rel error).
// ---------------------------------------------------------------------------
#define BM 128
#define KC 32
#define NCHUNK (IN_FEAT / KC)     // 16
#define A_STRIDE 36               // floats per A smem row (32 + 4 pad)
#define A_BUF_B (BM * A_STRIDE * 4)       // 18432 bytes per A buffer
#define B_BUF_B (KC * 128 * 4)            // 16384 bytes per B buffer (fragment order)
#define GEMM_SMEM (2 * A_BUF_B + 2 * B_BUF_B)   // 69632 bytes

__device__ __forceinline__ float tf32_hi(float x) {
    return __uint_as_float(__float_as_uint(x) & 0xFFFFE000u);
}

#define MMA_TF32(cc, aa, b0, b1)                                               \
    asm volatile(                                                              \
        "mma.sync.aligned.m16n8k8.row.col.f32.tf32.tf32.f32 "                  \
        "{%0,%1,%2,%3}, {%4,%5,%6,%7}, {%8,%9}, {%0,%1,%2,%3};"                \
        : "+f"((cc)[0]), "+f"((cc)[1]), "+f"((cc)[2]), "+f"((cc)[3])           \
        : "r"((aa)[0]), "r"((aa)[1]), "r"((aa)[2]), "r"((aa)[3]),              \
          "r"(b0), "r"(b1))

__global__ __launch_bounds__(256, 2) void gemm_mma_kernel(
    const float* __restrict__ A)   // feat [N_NODES, 512]
{
    extern __shared__ char smem[];
    float* sA[2] = { (float*)smem, (float*)(smem + A_BUF_B) };
    char*  sB[2] = { smem + 2 * A_BUF_B, smem + 2 * A_BUF_B + B_BUF_B };
    const uint32_t sA_u[2] = { smem_u32(sA[0]), smem_u32(sA[1]) };
    const uint32_t sB_u[2] = { smem_u32(sB[0]), smem_u32(sB[1]) };

    const int tid  = threadIdx.x;
    const int wid  = tid >> 5;
    const int lane = tid & 31;
    const int g    = lane >> 2;    // 0..7
    const int t4   = lane & 3;     // 0..3
    const int wm   = wid & 3;      // warp m index
    const int wn   = wid >> 2;     // warp n index
    const int m0   = blockIdx.x * BM;

    // A fill mapping: thread owns 4 (m, k4) slots per chunk
    const int fm[4] = { (0 * 256 + tid) >> 3, (1 * 256 + tid) >> 3,
                        (2 * 256 + tid) >> 3, (3 * 256 + tid) >> 3 };
    const int fk4 = tid & 7;

    // issue one chunk's async copies into buffer b
    auto stage = [&](int ch, int b) {
        const int k0 = ch * KC;
        #pragma unroll
        for (int it = 0; it < 4; ++it) {
            const int gm = m0 + fm[it];
            cp16(sA_u[b] + (fm[it] * A_STRIDE + fk4 * 4) * 4,
                 &A[(size_t)gm * IN_FEAT + k0 + fk4 * 4],
                 gm < N_NODES ? 16 : 0);
        }
        const char* bsrc = (const char*)g_Bfrag + (size_t)ch * B_BUF_B;
        #pragma unroll
        for (int j = 0; j < 4; ++j)
            cp16(sB_u[b] + j * 4096 + tid * 16, bsrc + j * 4096 + tid * 16, 16);
        cp_commit();
    };

    float c[2][8][4];
    #pragma unroll
    for (int i = 0; i < 2; i++)
        #pragma unroll
        for (int j = 0; j < 8; j++)
            #pragma unroll
            for (int q = 0; q < 4; q++) c[i][j][q] = 0.0f;

    stage(0, 0);

    for (int ch = 0; ch < NCHUNK; ++ch) {
        const int buf = ch & 1;
        if (ch + 1 < NCHUNK) {
            stage(ch + 1, buf ^ 1);
            cp_wait<1>();          // chunk ch's group complete
        } else {
            cp_wait<0>();
        }
        __syncthreads();

        const float* sa = sA[buf];
        // B base for this warp (fragment-ordered): slot (ks*16 + wn*8 + nb)
        const char* bw = sB[buf] + (wn * 8) * 256 + lane * 8;

        #pragma unroll
        for (int ks = 0; ks < 4; ++ks) {
            const int kb = ks * 8;
            const char* bk = bw + ks * 16 * 256;

            // A fragments: raw LDS, register hi/lo split
            uint32_t ah[2][4], al[2][4];
            #pragma unroll
            for (int mb = 0; mb < 2; ++mb) {
                const int r0 = wm * 32 + mb * 16 + g;
                const float a0 = sa[r0 * A_STRIDE + kb + t4];
                const float a1 = sa[(r0 + 8) * A_STRIDE + kb + t4];
                const float a2 = sa[r0 * A_STRIDE + kb + t4 + 4];
                const float a3 = sa[(r0 + 8) * A_STRIDE + kb + t4 + 4];
                const float h0 = tf32_hi(a0), h1 = tf32_hi(a1);
                const float h2 = tf32_hi(a2), h3 = tf32_hi(a3);
                ah[mb][0] = __float_as_uint(h0); al[mb][0] = __float_as_uint(a0 - h0);
                ah[mb][1] = __float_as_uint(h1); al[mb][1] = __float_as_uint(a1 - h1);
                ah[mb][2] = __float_as_uint(h2); al[mb][2] = __float_as_uint(a2 - h2);
                ah[mb][3] = __float_as_uint(h3); al[mb][3] = __float_as_uint(a3 - h3);
            }

            #pragma unroll
            for (int nb = 0; nb < 8; ++nb) {
                const float2 br = *(const float2*)(bk + nb * 256);
                const float bh0f = tf32_hi(br.x);
                const float bh1f = tf32_hi(br.y);
                const uint32_t bh0 = __float_as_uint(bh0f);
                const uint32_t bh1 = __float_as_uint(bh1f);
                const uint32_t bl0 = __float_as_uint(br.x - bh0f);
                const uint32_t bl1 = __float_as_uint(br.y - bh1f);
                #pragma unroll
                for (int mb = 0; mb < 2; ++mb) {
                    MMA_TF32(c[mb][nb], ah[mb], bh0, bh1);   // hi*hi
                    MMA_TF32(c[mb][nb], ah[mb], bl0, bl1);   // hi*lo
                    MMA_TF32(c[mb][nb], al[mb], bh0, bh1);   // lo*hi
                }
            }
        }
        __syncthreads();   // all warps done with buf before it is re-staged
    }

    // ---- epilogue ----
    #pragma unroll
    for (int mb = 0; mb < 2; ++mb) {
        #pragma unroll
        for (int half = 0; half < 2; ++half) {
            const int row = m0 + wm * 32 + mb * 16 + g + half * 8;
            if (row < N_NODES) {
                #pragma unroll
                for (int nb = 0; nb < 8; ++nb) {
                    const int col = wn * 64 + nb * 8 + 2 * t4;
                    float2 v = make_float2(c[mb][nb][2 * half],
                                           c[mb][nb][2 * half + 1]);
                    *(float2*)&g_x[(size_t)row * OUT_FEAT + col] = v;
                }
            }
        }
    }
}

// ---------------------------------------------------------------------------
// Kernel 3: SpMM (warp per row, no atomics) + multispike epilogue.
// ---------------------------------------------------------------------------
__device__ __forceinline__ float multispike(float x) {
    return floorf(fminf(fmaxf(4.0f * x, 0.0f), 4.0f) + 0.5f) * 0.25f;
}

__global__ __launch_bounds__(256) void spmm_kernel(
    const int*   __restrict__ cols,
    const float* __restrict__ ew,
    float*       __restrict__ out)
{
    const int warp = (blockIdx.x * blockDim.x + threadIdx.x) >> 5;
    const int lane = threadIdx.x & 31;
    if (warp >= N_NODES) return;

    const int e0 = g_row_ptr[warp];
    const int e1 = g_row_ptr[warp + 1];

    float4 acc = make_float4(0.f, 0.f, 0.f, 0.f);
    const int fo = lane * 4;

    int e = e0;
    for (; e + 3 < e1; e += 4) {
        int   cc[4];
        float ww[4];
        #pragma unroll
        for (int j = 0; j < 4; ++j) { cc[j] = __ldg(&cols[e + j]); ww[j] = __ldg(&ew[e + j]); }
        #pragma unroll
        for (int j = 0; j < 4; ++j) {
            const float4 v = *(const float4*)&g_x[(size_t)cc[j] * OUT_FEAT + fo];
            acc.x = fmaf(ww[j], v.x, acc.x); acc.y = fmaf(ww[j], v.y, acc.y);
            acc.z = fmaf(ww[j], v.z, acc.z); acc.w = fmaf(ww[j], v.w, acc.w);
        }
    }
    for (; e < e1; ++e) {
        const int   c0 = __ldg(&cols[e]);
        const float w0 = __ldg(&ew[e]);
        const float4 v0 = *(const float4*)&g_x[(size_t)c0 * OUT_FEAT + fo];
        acc.x = fmaf(w0, v0.x, acc.x); acc.y = fmaf(w0, v0.y, acc.y);
        acc.z = fmaf(w0, v0.z, acc.z); acc.w = fmaf(w0, v0.w, acc.w);
    }

    acc.x = multispike(acc.x);
    acc.y = multispike(acc.y);
    acc.z = multispike(acc.z);
    acc.w = multispike(acc.w);
    *(float4*)&out[(size_t)warp * OUT_FEAT + fo] = acc;
}

// ---------------------------------------------------------------------------
extern "C" void kernel_launch(void* const* d_in, const int* in_sizes, int n_in,
                              void* d_out, int out_size) {
    const float* feat   = (const float*)d_in[0];
    const float* weight = (const float*)d_in[1];
    const int*   rows   = (const int*)d_in[2];
    const int*   cols   = (const int*)d_in[3];
    const float* ew     = (const float*)d_in[4];
    float* out = (float*)d_out;

    cudaFuncSetAttribute(gemm_mma_kernel,
                         cudaFuncAttributeMaxDynamicSharedMemorySize, GEMM_SMEM);

    row_ptr_kernel<<<(N_EDGES / 4 + 255) / 256, 256>>>(rows);
    bfrag_kernel<<<(64 * 16 * 32 + 255) / 256, 256>>>(weight);
    gemm_mma_kernel<<<(N_NODES + BM - 1) / BM, 256, GEMM_SMEM>>>(feat);
    spmm_kernel<<<(N_NODES * 32 + 255) / 256, 256>>>(cols, ew, out);
}

// round 6
// speedup vs baseline: 1.2993x; 1.0316x over previous
#include <cuda_runtime.h>
#include <cstdint>
#include <math.h>

#define N_NODES 50000
#define N_EDGES 800000
#define IN_FEAT 512
#define OUT_FEAT 128

// Scratch: intermediate x = feat @ W, CSR row pointers, fragment-ordered W.
__device__ float  g_x[(size_t)N_NODES * OUT_FEAT];
__device__ int    g_row_ptr[N_NODES + 1];
// B fragments: idx = (kk*16 + nbg)*32 + lane, value {B[kk*8+t4][n], B[kk*8+t4+4][n]}
// with t4 = lane&3, g = lane>>2, n = nbg*8 + g;  kk = 0..63, nbg = 0..15.
__device__ float2 g_Bfrag[64 * 16 * 32];

// ---------------------------------------------------------------------------
// cp.async helpers (Ampere+ PTX, arch-portable)
// ---------------------------------------------------------------------------
__device__ __forceinline__ uint32_t smem_u32(const void* p) {
    uint32_t a;
    asm("{ .reg .u64 t; cvta.to.shared.u64 t, %1; cvt.u32.u64 %0, t; }"
        : "=r"(a) : "l"(p));
    return a;
}
__device__ __forceinline__ void cp16(uint32_t dst, const void* src, int src_bytes) {
    asm volatile("cp.async.cg.shared.global [%0], [%1], 16, %2;"
                 :: "r"(dst), "l"(src), "r"(src_bytes));
}
__device__ __forceinline__ void cp_commit() {
    asm volatile("cp.async.commit_group;" ::: "memory");
}
template <int N>
__device__ __forceinline__ void cp_wait() {
    asm volatile("cp.async.wait_group %0;" :: "n"(N) : "memory");
}

// ---------------------------------------------------------------------------
// Kernel 1: CSR row pointers via vectorized edge-boundary scatter.
// ---------------------------------------------------------------------------
__global__ void row_ptr_kernel(const int* __restrict__ rows) {
    const int t = blockIdx.x * blockDim.x + threadIdx.x;
    const int e0 = t * 4;
    if (e0 >= N_EDGES) return;
    const int4 r4 = *(const int4*)&rows[e0];
    int prev = (t == 0) ? -1 : __ldg(&rows[e0 - 1]);
    int rv[4] = {r4.x, r4.y, r4.z, r4.w};
    #pragma unroll
    for (int j = 0; j < 4; ++j) {
        for (int r = prev + 1; r <= rv[j]; ++r) g_row_ptr[r] = e0 + j;
        prev = rv[j];
    }
    if (e0 + 4 == N_EDGES) {
        for (int r = prev + 1; r <= N_NODES; ++r) g_row_ptr[r] = N_EDGES;
    }
}

// ---------------------------------------------------------------------------
// Kernel 1b: permute weight into MMA fragment order (raw fp32, split later).
// ---------------------------------------------------------------------------
__global__ void bfrag_kernel(const float* __restrict__ B) {
    const int idx = blockIdx.x * blockDim.x + threadIdx.x;   // 0..32767
    if (idx >= 64 * 16 * 32) return;
    const int lane = idx & 31;
    const int nbg  = (idx >> 5) & 15;
    const int kk   = idx >> 9;
    const int t4   = lane & 3;
    const int g    = lane >> 2;
    const int n    = nbg * 8 + g;
    const int k    = kk * 8 + t4;
    g_Bfrag[idx] = make_float2(__ldg(&B[(size_t)k * OUT_FEAT + n]),
                               __ldg(&B[(size_t)(k + 4) * OUT_FEAT + n]));
}

// ---------------------------------------------------------------------------
// Kernel 2: 3xTF32 GEMM via mma.sync, cp.async pipelined, FINE-GRAINED tiles.
//   g_x[M,128] = feat[M,512] @ W[512,128]
// CTA tile 32(M) x 128(N), 128 threads = 4 warps (one per SMSP).
// Warp tile 32(M) x 32(N): mb in {0,1} (m16 halves), nb in {0..3}.
// 1563 CTAs; dynamic smem padded to 56 KB to pin occupancy at 4 ->
// ~10.6 CTAs/SM over 4 slots -> ~88% tail utilization (vs ~70% at BM=128).
// hi/lo tf32 register split; hh + hl + lh in fp32 (~2^-22 rel error).
// ---------------------------------------------------------------------------
#define BM 32
#define KC 32
#define NCHUNK (IN_FEAT / KC)     // 16
#define A_STRIDE 36               // floats per A smem row (32 + 4 pad)
#define A_BUF_B (BM * A_STRIDE * 4)       // 4608 bytes per A buffer
#define B_BUF_B (KC * 128 * 4)            // 16384 bytes per B buffer
#define GEMM_SMEM 57344                   // padded to force occupancy = 4

__device__ __forceinline__ float tf32_hi(float x) {
    return __uint_as_float(__float_as_uint(x) & 0xFFFFE000u);
}

#define MMA_TF32(cc, aa, b0, b1)                                               \
    asm volatile(                                                              \
        "mma.sync.aligned.m16n8k8.row.col.f32.tf32.tf32.f32 "                  \
        "{%0,%1,%2,%3}, {%4,%5,%6,%7}, {%8,%9}, {%0,%1,%2,%3};"                \
        : "+f"((cc)[0]), "+f"((cc)[1]), "+f"((cc)[2]), "+f"((cc)[3])           \
        : "r"((aa)[0]), "r"((aa)[1]), "r"((aa)[2]), "r"((aa)[3]),              \
          "r"(b0), "r"(b1))

__global__ __launch_bounds__(128) void gemm_mma_kernel(
    const float* __restrict__ A)   // feat [N_NODES, 512]
{
    extern __shared__ char smem[];
    float* sA[2] = { (float*)smem, (float*)(smem + A_BUF_B) };
    char*  sB[2] = { smem + 2 * A_BUF_B, smem + 2 * A_BUF_B + B_BUF_B };
    const uint32_t sA_u[2] = { smem_u32(sA[0]), smem_u32(sA[1]) };
    const uint32_t sB_u[2] = { smem_u32(sB[0]), smem_u32(sB[1]) };

    const int tid  = threadIdx.x;
    const int wn   = tid >> 5;     // warp n index 0..3
    const int lane = tid & 31;
    const int g    = lane >> 2;    // 0..7
    const int t4   = lane & 3;     // 0..3
    const int m0   = blockIdx.x * BM;

    // A fill mapping: 256 float4 slots (32 rows x 8 k4), 2 per thread.
    const int fm[2] = { (0 * 128 + tid) >> 3, (1 * 128 + tid) >> 3 };
    const int fk4 = tid & 7;

    auto stage = [&](int ch, int b) {
        const int k0 = ch * KC;
        #pragma unroll
        for (int it = 0; it < 2; ++it) {
            const int gm = m0 + fm[it];
            cp16(sA_u[b] + (fm[it] * A_STRIDE + fk4 * 4) * 4,
                 &A[(size_t)gm * IN_FEAT + k0 + fk4 * 4],
                 gm < N_NODES ? 16 : 0);
        }
        const char* bsrc = (const char*)g_Bfrag + (size_t)ch * B_BUF_B;
        #pragma unroll
        for (int j = 0; j < 8; ++j)
            cp16(sB_u[b] + j * 2048 + tid * 16, bsrc + j * 2048 + tid * 16, 16);
        cp_commit();
    };

    float c[2][4][4];
    #pragma unroll
    for (int i = 0; i < 2; i++)
        #pragma unroll
        for (int j = 0; j < 4; j++)
            #pragma unroll
            for (int q = 0; q < 4; q++) c[i][j][q] = 0.0f;

    stage(0, 0);

    for (int ch = 0; ch < NCHUNK; ++ch) {
        const int buf = ch & 1;
        if (ch + 1 < NCHUNK) {
            stage(ch + 1, buf ^ 1);
            cp_wait<1>();
        } else {
            cp_wait<0>();
        }
        __syncthreads();

        const float* sa = sA[buf];
        // warp wn uses fragment slots (ks*16 + wn*4 + nb)
        const char* bw = sB[buf] + (wn * 4) * 256 + lane * 8;

        #pragma unroll
        for (int ks = 0; ks < 4; ++ks) {
            const int kb = ks * 8;
            const char* bk = bw + ks * 16 * 256;

            // A fragments: raw LDS (conflict-free), register hi/lo split
            uint32_t ah[2][4], al[2][4];
            #pragma unroll
            for (int mb = 0; mb < 2; ++mb) {
                const int r0 = mb * 16 + g;
                const float a0 = sa[r0 * A_STRIDE + kb + t4];
                const float a1 = sa[(r0 + 8) * A_STRIDE + kb + t4];
                const float a2 = sa[r0 * A_STRIDE + kb + t4 + 4];
                const float a3 = sa[(r0 + 8) * A_STRIDE + kb + t4 + 4];
                const float h0 = tf32_hi(a0), h1 = tf32_hi(a1);
                const float h2 = tf32_hi(a2), h3 = tf32_hi(a3);
                ah[mb][0] = __float_as_uint(h0); al[mb][0] = __float_as_uint(a0 - h0);
                ah[mb][1] = __float_as_uint(h1); al[mb][1] = __float_as_uint(a1 - h1);
                ah[mb][2] = __float_as_uint(h2); al[mb][2] = __float_as_uint(a2 - h2);
                ah[mb][3] = __float_as_uint(h3); al[mb][3] = __float_as_uint(a3 - h3);
            }

            #pragma unroll
            for (int nb = 0; nb < 4; ++nb) {
                const float2 br = *(const float2*)(bk + nb * 256);
                const float bh0f = tf32_hi(br.x);
                const float bh1f = tf32_hi(br.y);
                const uint32_t bh0 = __float_as_uint(bh0f);
                const uint32_t bh1 = __float_as_uint(bh1f);
                const uint32_t bl0 = __float_as_uint(br.x - bh0f);
                const uint32_t bl1 = __float_as_uint(br.y - bh1f);
                #pragma unroll
                for (int mb = 0; mb < 2; ++mb) {
                    MMA_TF32(c[mb][nb], ah[mb], bh0, bh1);   // hi*hi
                    MMA_TF32(c[mb][nb], ah[mb], bl0, bl1);   // hi*lo
                    MMA_TF32(c[mb][nb], al[mb], bh0, bh1);   // lo*hi
                }
            }
        }
        __syncthreads();
    }

    // ---- epilogue ----
    #pragma unroll
    for (int mb = 0; mb < 2; ++mb) {
        #pragma unroll
        for (int half = 0; half < 2; ++half) {
            const int row = m0 + mb * 16 + g + half * 8;
            if (row < N_NODES) {
                #pragma unroll
                for (int nb = 0; nb < 4; ++nb) {
                    const int col = wn * 32 + nb * 8 + 2 * t4;
                    float2 v = make_float2(c[mb][nb][2 * half],
                                           c[mb][nb][2 * half + 1]);
                    *(float2*)&g_x[(size_t)row * OUT_FEAT + col] = v;
                }
            }
        }
    }
}

// ---------------------------------------------------------------------------
// Kernel 3: SpMM (warp per row, no atomics) + multispike epilogue.
// ---------------------------------------------------------------------------
__device__ __forceinline__ float multispike(float x) {
    return floorf(fminf(fmaxf(4.0f * x, 0.0f), 4.0f) + 0.5f) * 0.25f;
}

__global__ __launch_bounds__(256) void spmm_kernel(
    const int*   __restrict__ cols,
    const float* __restrict__ ew,
    float*       __restrict__ out)
{
    const int warp = (blockIdx.x * blockDim.x + threadIdx.x) >> 5;
    const int lane = threadIdx.x & 31;
    if (warp >= N_NODES) return;

    const int e0 = g_row_ptr[warp];
    const int e1 = g_row_ptr[warp + 1];

    float4 acc = make_float4(0.f, 0.f, 0.f, 0.f);
    const int fo = lane * 4;

    int e = e0;
    for (; e + 3 < e1; e += 4) {
        int   cc[4];
        float ww[4];
        #pragma unroll
        for (int j = 0; j < 4; ++j) { cc[j] = __ldg(&cols[e + j]); ww[j] = __ldg(&ew[e + j]); }
        #pragma unroll
        for (int j = 0; j < 4; ++j) {
            const float4 v = *(const float4*)&g_x[(size_t)cc[j] * OUT_FEAT + fo];
            acc.x = fmaf(ww[j], v.x, acc.x); acc.y = fmaf(ww[j], v.y, acc.y);
            acc.z = fmaf(ww[j], v.z, acc.z); acc.w = fmaf(ww[j], v.w, acc.w);
        }
    }
    for (; e < e1; ++e) {
        const int   c0 = __ldg(&cols[e]);
        const float w0 = __ldg(&ew[e]);
        const float4 v0 = *(const float4*)&g_x[(size_t)c0 * OUT_FEAT + fo];
        acc.x = fmaf(w0, v0.x, acc.x); acc.y = fmaf(w0, v0.y, acc.y);
        acc.z = fmaf(w0, v0.z, acc.z); acc.w = fmaf(w0, v0.w, acc.w);
    }

    acc.x = multispike(acc.x);
    acc.y = multispike(acc.y);
    acc.z = multispike(acc.z);
    acc.w = multispike(acc.w);
    *(float4*)&out[(size_t)warp * OUT_FEAT + fo] = acc;
}

// ---------------------------------------------------------------------------
extern "C" void kernel_launch(void* const* d_in, const int* in_sizes, int n_in,
                              void* d_out, int out_size) {
    const float* feat   = (const float*)d_in[0];
    const float* weight = (const float*)d_in[1];
    const int*   rows   = (const int*)d_in[2];
    const int*   cols   = (const int*)d_in[3];
    const float* ew     = (const float*)d_in[4];
    float* out = (float*)d_out;

    cudaFuncSetAttribute(gemm_mma_kernel,
                         cudaFuncAttributeMaxDynamicSharedMemorySize, GEMM_SMEM);

    row_ptr_kernel<<<(N_EDGES / 4 + 255) / 256, 256>>>(rows);
    bfrag_kernel<<<(64 * 16 * 32 + 255) / 256, 256>>>(weight);
    gemm_mma_kernel<<<(N_NODES + BM - 1) / BM, 128, GEMM_SMEM>>>(feat);
    spmm_kernel<<<(N_NODES * 32 + 255) / 256, 256>>>(cols, ew, out);
}